// round 6
// baseline (speedup 1.0000x reference)
#include <cuda_runtime.h>

// Problem constants
#define BATCH   64
#define TLEN    8192
#define DECL    64
#define NWIN    (TLEN - DECL)      // 8128
#define CHUNKS  2
#define WPC     (NWIN / CHUNKS)    // 4064 windows per chunk
#define TPB     512
#define WPT     8                  // 512*8 = 4096 >= 4064

// smem x tile: max local read index = 4064 + 71 = 4135
#define XTILE   4136
#define XTILEP  (XTILE + XTILE / 8)   // pad i -> i + i/8: stride-8 refill -> stride 9, conflict-free

// Cross-block combine scratch (zero-init; kernel restores zeros after use so
// every graph replay sees identical initial state).
__device__ unsigned long long g_best[BATCH]; // max over ~key
__device__ unsigned int       g_cnt[BATCH];

__device__ __forceinline__ int padi(int i) { return i + (i >> 3); }

union F2U { float2 f; unsigned long long u; };

// Packed dual FMA: d = a*b + d (per 32-bit lane). Only reachable via PTX.
__device__ __forceinline__ void ffma2(F2U& d, const F2U& a, const F2U& b) {
    asm("fma.rn.f32x2 %0, %1, %2, %0;" : "+l"(d.u) : "l"(a.u), "l"(b.u));
}

__global__ __launch_bounds__(TPB, 1)
void match_kernel(const float* __restrict__ X_in,
                  const float* __restrict__ X_out,
                  float* __restrict__ out)
{
    __shared__ float  xs[XTILEP];
    __shared__ float2 ys2[DECL];               // (y_j, y_j) pairs for LDS.64 broadcast
    __shared__ unsigned long long red[TPB / 32];
    __shared__ int lastFlag;

    const int c    = blockIdx.x;    // chunk (0..1)
    const int b    = blockIdx.y;    // batch
    const int tid  = threadIdx.x;
    const int lane = tid & 31;
    const int warp = tid >> 5;

    const float* xb = X_in + (size_t)b * TLEN;
    const int base  = c * WPC;      // 0 or 4064 (multiple of 16 -> float4 aligned)

    // y first (overlaps with x tile LDGs)
    if (tid < DECL) {
        float v = X_out[b * DECL + tid];
        ys2[tid] = make_float2(v, v);
    }
    // Vectorized tile load
    {
        const float4* xb4 = (const float4*)(xb + base);
        for (int i4 = tid; i4 < XTILE / 4; i4 += TPB) {
            int i = i4 * 4;
            if (base + i + 3 < TLEN) {
                float4 v = xb4[i4];
                xs[padi(i + 0)] = v.x;
                xs[padi(i + 1)] = v.y;
                xs[padi(i + 2)] = v.z;
                xs[padi(i + 3)] = v.w;
            } else {
                #pragma unroll
                for (int k = 0; k < 4; ++k) {
                    int g = base + i + k;
                    xs[padi(i + k)] = (g < TLEN) ? xb[g] : 0.0f;
                }
            }
        }
    }
    __syncthreads();

    const int l0 = tid * WPT;

    // Packed sliding ring: at step j, pr[(j+k)&3] = (x[l0+j+k], x[l0+j+k+4]).
    F2U pr[4];
    #pragma unroll
    for (int k = 0; k < 4; ++k) {
        pr[k].f.x = xs[padi(l0 + k)];
        pr[k].f.y = xs[padi(l0 + k + 4)];
    }

    F2U pacc[4];                    // pacc[k] = (acc_k, acc_{k+4})
    #pragma unroll
    for (int k = 0; k < 4; ++k) { pacc[k].f.x = 0.f; pacc[k].f.y = 0.f; }
    float sx2 = 0.f;                // sum x^2 for window w=0

    // Software-pipelined y broadcast: yy holds ys2[j], loaded one step ahead.
    F2U yy; yy.f = ys2[0];
    #pragma unroll
    for (int j = 0; j < DECL; ++j) {
        F2U yn;
        if (j + 1 < DECL) yn.f = ys2[j + 1];      // prefetch next pair
        float nh = xs[padi(l0 + j + 8)];          // prefetch ring refill
        ffma2(pacc[0], pr[(j + 0) & 3], yy);
        ffma2(pacc[1], pr[(j + 1) & 3], yy);
        ffma2(pacc[2], pr[(j + 2) & 3], yy);
        ffma2(pacc[3], pr[(j + 3) & 3], yy);
        float vlo = pr[j & 3].f.x;                // leaving element x[l0+j]
        sx2 = fmaf(vlo, vlo, sx2);
        pr[j & 3].f.x = pr[j & 3].f.y;            // pair shift
        pr[j & 3].f.y = nh;
        yy = yn;
    }
    // After loop: pr[k] = (x[l0+64+k], x[l0+68+k]), k=0..3.

    float acc[8];
    #pragma unroll
    for (int k = 0; k < 4; ++k) { acc[k] = pacc[k].f.x; acc[k + 4] = pacc[k].f.y; }

    float score[8];
    score[0] = fmaf(-2.0f, acc[0], sx2);
    float s = sx2;
    #pragma unroll
    for (int w = 1; w < 8; ++w) {
        float xin  = (w <= 4) ? pr[w - 1].f.x : pr[w - 5].f.y;  // x[l0+w+63]
        float xout = xs[padi(l0 + w - 1)];                       // x[l0+w-1]
        s = fmaf(xin, xin, s);
        s = fmaf(-xout, xout, s);
        score[w] = fmaf(-2.0f, acc[w], s);
    }

    // Thread-local argmin, first-index tie-break, monotonic packed key.
    unsigned long long bestik = 0ULL;       // max over ~key
    #pragma unroll
    for (int w = 0; w < 8; ++w) {
        int lw    = l0 + w;
        int gidx  = base + lw;
        bool valid = (lw < WPC);
        float sc  = valid ? score[w] : __int_as_float(0x7F800000); // +inf
        unsigned u = __float_as_uint(sc);
        unsigned m = u ^ ((unsigned)((int)u >> 31) | 0x80000000u); // monotonic map
        unsigned long long key = ((unsigned long long)m << 32) | (unsigned)gidx;
        unsigned long long ik  = ~key;      // max(ik) == min(key); tie -> smaller idx
        bestik = bestik > ik ? bestik : ik;
    }

    // Warp reduce (max over ~key)
    #pragma unroll
    for (int o = 16; o; o >>= 1) {
        unsigned long long v = __shfl_down_sync(0xFFFFFFFFu, bestik, o);
        bestik = bestik > v ? bestik : v;
    }
    if (lane == 0) red[warp] = bestik;
    __syncthreads();

    // First warp reduces the 16 per-warp keys.
    if (warp == 0) {
        unsigned long long k = (lane < TPB / 32) ? red[lane] : 0ULL;
        #pragma unroll
        for (int o = 8; o; o >>= 1) {
            unsigned long long v = __shfl_down_sync(0xFFFFFFFFu, k, o);
            k = k > v ? k : v;
        }
        if (lane == 0) {
            atomicMax(&g_best[b], k);
            __threadfence();
            unsigned prev = atomicAdd(&g_cnt[b], 1u);
            lastFlag = (prev == CHUNKS - 1) ? 1 : 0;
        }
    }
    __syncthreads();

    // Last block for this batch gathers output and restores scratch.
    if (lastFlag) {
        unsigned long long k = atomicMax(&g_best[b], 0ULL); // atomic read
        int start = (int)((~k) & 0xFFFFFFFFull);
        if (tid < DECL) out[b * DECL + tid] = xb[start + tid];
        __syncthreads();
        if (tid == 0) { g_best[b] = 0ULL; g_cnt[b] = 0u; }
    }
}

extern "C" void kernel_launch(void* const* d_in, const int* in_sizes, int n_in,
                              void* d_out, int out_size)
{
    // inputs: 0=feats_in (unused), 1=X_in, 2=feats_out (unused), 3=X_out
    const float* X_in  = (const float*)d_in[1];
    const float* X_out = (const float*)d_in[3];
    float* out = (float*)d_out;

    dim3 grid(CHUNKS, BATCH);
    match_kernel<<<grid, TPB>>>(X_in, X_out, out);
}

// round 8
// speedup vs baseline: 1.9329x; 1.9329x over previous
#include <cuda_runtime.h>

// Problem constants
#define BATCH   64
#define TLEN    8192
#define DECL    64
#define NWIN    (TLEN - DECL)      // 8128
#define CHUNKS  8
#define WPC     (NWIN / CHUNKS)    // 1016 windows per chunk
#define TPB     128
#define WPT     8                  // 128*8 = 1024 >= 1016

// smem x tile: max local read index = 1016 + 71 = 1087
#define XTILE   1088
#define XTILEP  (XTILE + XTILE / 8)   // pad i -> i + i/8: stride-8 refill -> stride 9, conflict-free

// Cross-block combine scratch (zero-init; kernel restores zeros after use so
// every graph replay sees identical initial state).
__device__ unsigned long long g_best[BATCH]; // max over ~key
__device__ unsigned int       g_cnt[BATCH];

__device__ __forceinline__ int padi(int i) { return i + (i >> 3); }

union F2U { float2 f; unsigned long long u; };

// Packed dual FMA: d = a*b + d (per 32-bit lane). Only reachable via PTX.
__device__ __forceinline__ void ffma2(F2U& d, const F2U& a, const F2U& b) {
    asm("fma.rn.f32x2 %0, %1, %2, %0;" : "+l"(d.u) : "l"(a.u), "l"(b.u));
}

__global__ __launch_bounds__(TPB, 8)
void match_kernel(const float* __restrict__ X_in,
                  const float* __restrict__ X_out,
                  float* __restrict__ out)
{
    __shared__ float  xs[XTILEP];
    __shared__ float2 ys2[DECL];               // (y_j, y_j) pairs for LDS.64 broadcast
    __shared__ unsigned long long red[TPB / 32];
    __shared__ int lastFlag;

    const int c   = blockIdx.x;     // chunk
    const int b   = blockIdx.y;     // batch
    const int tid = threadIdx.x;

    const float* xb = X_in + (size_t)b * TLEN;
    const int base  = c * WPC;      // multiple of 8 -> float4-aligned (1016%4==0? 1016/4=254 yes)

    // y first (overlaps with x tile LDGs)
    if (tid < DECL) {
        float v = X_out[b * DECL + tid];
        ys2[tid] = make_float2(v, v);
    }
    // Vectorized tile load: 272 float4 loads, ~2.1 per thread, high MLP.
    {
        const float4* xb4 = (const float4*)(xb + base);
        for (int i4 = tid; i4 < XTILE / 4; i4 += TPB) {
            int i = i4 * 4;
            if (base + i + 3 < TLEN) {
                float4 v = xb4[i4];
                xs[padi(i + 0)] = v.x;
                xs[padi(i + 1)] = v.y;
                xs[padi(i + 2)] = v.z;
                xs[padi(i + 3)] = v.w;
            } else {
                #pragma unroll
                for (int k = 0; k < 4; ++k) {
                    int g = base + i + k;
                    xs[padi(i + k)] = (g < TLEN) ? xb[g] : 0.0f;
                }
            }
        }
    }
    __syncthreads();

    const int l0 = tid * WPT;

    // Packed sliding ring: at step j, pr[(j+k)&3] = (x[l0+j+k], x[l0+j+k+4]).
    F2U pr[4];
    #pragma unroll
    for (int k = 0; k < 4; ++k) {
        pr[k].f.x = xs[padi(l0 + k)];
        pr[k].f.y = xs[padi(l0 + k + 4)];
    }

    F2U pacc[4];                    // pacc[k] = (acc_k, acc_{k+4})
    #pragma unroll
    for (int k = 0; k < 4; ++k) { pacc[k].f.x = 0.f; pacc[k].f.y = 0.f; }
    float sx2 = 0.f;                // sum x^2 for window w=0

    // y broadcast pipelined 2 iterations deep: yy = ys2[j], yn = ys2[j+1].
    F2U yy, yn;
    yy.f = ys2[0];
    yn.f = ys2[1];
    #pragma unroll
    for (int j = 0; j < DECL; ++j) {
        F2U y2;
        if (j + 2 < DECL) y2.f = ys2[j + 2];      // prefetch 2 ahead
        float nh = xs[padi(l0 + j + 8)];          // ring refill (4 steps of slack)
        ffma2(pacc[0], pr[(j + 0) & 3], yy);
        ffma2(pacc[1], pr[(j + 1) & 3], yy);
        ffma2(pacc[2], pr[(j + 2) & 3], yy);
        ffma2(pacc[3], pr[(j + 3) & 3], yy);
        float vlo = pr[j & 3].f.x;                // leaving element x[l0+j]
        sx2 = fmaf(vlo, vlo, sx2);
        pr[j & 3].f.x = pr[j & 3].f.y;            // pair shift
        pr[j & 3].f.y = nh;
        yy = yn;
        yn = y2;
    }
    // After loop: pr[k] = (x[l0+64+k], x[l0+68+k]), k=0..3.

    float acc[8];
    #pragma unroll
    for (int k = 0; k < 4; ++k) { acc[k] = pacc[k].f.x; acc[k + 4] = pacc[k].f.y; }

    float score[8];
    score[0] = fmaf(-2.0f, acc[0], sx2);
    float s = sx2;
    #pragma unroll
    for (int w = 1; w < 8; ++w) {
        float xin  = (w <= 4) ? pr[w - 1].f.x : pr[w - 5].f.y;  // x[l0+w+63]
        float xout = xs[padi(l0 + w - 1)];                       // x[l0+w-1]
        s = fmaf(xin, xin, s);
        s = fmaf(-xout, xout, s);
        score[w] = fmaf(-2.0f, acc[w], s);
    }

    // Thread-local argmin, first-index tie-break, monotonic packed key.
    unsigned long long bestik = 0ULL;       // max over ~key
    #pragma unroll
    for (int w = 0; w < 8; ++w) {
        int lw    = l0 + w;
        int gidx  = base + lw;
        bool valid = (lw < WPC);
        float sc  = valid ? score[w] : __int_as_float(0x7F800000); // +inf
        unsigned u = __float_as_uint(sc);
        unsigned m = u ^ ((unsigned)((int)u >> 31) | 0x80000000u); // monotonic map
        unsigned long long key = ((unsigned long long)m << 32) | (unsigned)gidx;
        unsigned long long ik  = ~key;      // max(ik) == min(key); tie -> smaller idx
        bestik = bestik > ik ? bestik : ik;
    }

    // Warp reduce (max over ~key)
    #pragma unroll
    for (int o = 16; o; o >>= 1) {
        unsigned long long v = __shfl_down_sync(0xFFFFFFFFu, bestik, o);
        bestik = bestik > v ? bestik : v;
    }
    if ((tid & 31) == 0) red[tid >> 5] = bestik;
    __syncthreads();

    if (tid == 0) {
        unsigned long long k = red[0];
        #pragma unroll
        for (int i = 1; i < TPB / 32; ++i) k = k > red[i] ? k : red[i];
        atomicMax(&g_best[b], k);
        __threadfence();
        unsigned prev = atomicAdd(&g_cnt[b], 1u);
        lastFlag = (prev == CHUNKS - 1) ? 1 : 0;
    }
    __syncthreads();

    // Last block for this batch gathers output and restores scratch.
    // After the fence+counter handshake, all prior atomicMax results are
    // visible; a volatile read suffices (no ATOMG round-trip).
    if (lastFlag) {
        unsigned long long k = *(volatile unsigned long long*)&g_best[b];
        int start = (int)((~k) & 0xFFFFFFFFull);
        if (tid < DECL) out[b * DECL + tid] = xb[start + tid];
        __syncthreads();
        if (tid == 0) { g_best[b] = 0ULL; g_cnt[b] = 0u; }
    }
}

extern "C" void kernel_launch(void* const* d_in, const int* in_sizes, int n_in,
                              void* d_out, int out_size)
{
    // inputs: 0=feats_in (unused), 1=X_in, 2=feats_out (unused), 3=X_out
    const float* X_in  = (const float*)d_in[1];
    const float* X_out = (const float*)d_in[3];
    float* out = (float*)d_out;

    dim3 grid(CHUNKS, BATCH);
    match_kernel<<<grid, TPB>>>(X_in, X_out, out);
}

// round 9
// speedup vs baseline: 1.9791x; 1.0239x over previous
#include <cuda_runtime.h>

// Problem constants
#define BATCH   64
#define TLEN    8192
#define DECL    64
#define NWIN    (TLEN - DECL)      // 8128
#define CHUNKS  8
#define WPC     (NWIN / CHUNKS)    // 1016 windows per chunk = 127*8
#define TPB     128
#define WPT     8                  // 128*8 = 1024 >= 1016; only tid==127 fully invalid

// smem x tile: max local read index = 1016 + 71 = 1087
#define XTILE   1088
#define XTILEP  (XTILE + XTILE / 8)   // pad i -> i + i/8: stride-8 refill -> stride 9, conflict-free

// Cross-block combine scratch (zero-init; kernel restores zeros after use so
// every graph replay sees identical initial state).
__device__ unsigned long long g_best[BATCH]; // max over ~key
__device__ unsigned int       g_cnt[BATCH];

__device__ __forceinline__ int padi(int i) { return i + (i >> 3); }

union F2U { float2 f; unsigned long long u; };

// Packed dual FMA: d = a*b + d (per 32-bit lane). Only reachable via PTX.
__device__ __forceinline__ void ffma2(F2U& d, const F2U& a, const F2U& b) {
    asm("fma.rn.f32x2 %0, %1, %2, %0;" : "+l"(d.u) : "l"(a.u), "l"(b.u));
}

__global__ __launch_bounds__(TPB, 8)
void match_kernel(const float* __restrict__ X_in,
                  const float* __restrict__ X_out,
                  float* __restrict__ out)
{
    __shared__ float  xs[XTILEP];
    __shared__ float4 ys4[DECL / 2];           // (y_j, y_j, y_{j+1}, y_{j+1})
    __shared__ unsigned long long red[TPB / 32];
    __shared__ int lastFlag;

    const int c   = blockIdx.x;     // chunk
    const int b   = blockIdx.y;     // batch
    const int tid = threadIdx.x;

    const float* xb = X_in + (size_t)b * TLEN;
    const int base  = c * WPC;      // multiple of 8 -> float4-aligned

    // y first (overlaps with x tile LDGs): 32 threads build duplicated pairs.
    if (tid < DECL / 2) {
        float2 v = ((const float2*)(X_out + b * DECL))[tid];
        ys4[tid] = make_float4(v.x, v.x, v.y, v.y);
    }
    // Vectorized tile load: 272 float4 loads, ~2.1 per thread, high MLP.
    {
        const float4* xb4 = (const float4*)(xb + base);
        for (int i4 = tid; i4 < XTILE / 4; i4 += TPB) {
            int i = i4 * 4;
            if (base + i + 3 < TLEN) {
                float4 v = xb4[i4];
                xs[padi(i + 0)] = v.x;
                xs[padi(i + 1)] = v.y;
                xs[padi(i + 2)] = v.z;
                xs[padi(i + 3)] = v.w;
            } else {
                #pragma unroll
                for (int k = 0; k < 4; ++k) {
                    int g = base + i + k;
                    xs[padi(i + k)] = (g < TLEN) ? xb[g] : 0.0f;
                }
            }
        }
    }
    __syncthreads();

    const int l0 = tid * WPT;

    // Packed sliding ring: at step j, pr[(j+k)&3] = (x[l0+j+k], x[l0+j+k+4]).
    F2U pr[4];
    #pragma unroll
    for (int k = 0; k < 4; ++k) {
        pr[k].f.x = xs[padi(l0 + k)];
        pr[k].f.y = xs[padi(l0 + k + 4)];
    }

    F2U pacc[4];                    // pacc[k] = (acc_k, acc_{k+4})
    #pragma unroll
    for (int k = 0; k < 4; ++k) { pacc[k].f.x = 0.f; pacc[k].f.y = 0.f; }
    float sx2 = 0.f;                // sum x^2 for window w=0

    // Main loop: 2 j-steps per iteration, one LDS.128 delivers both y pairs.
    // Fully unrolled straight-line body; ptxas hoists the LDS loads.
    #pragma unroll
    for (int j2 = 0; j2 < DECL / 2; ++j2) {
        const int j = 2 * j2;
        float4 yq = ys4[j2];                      // (yj,yj,yj1,yj1)

        // step j (even)
        {
            F2U ya; ya.f.x = yq.x; ya.f.y = yq.y;
            float nh = xs[padi(l0 + j + 8)];
            ffma2(pacc[0], pr[(j + 0) & 3], ya);
            ffma2(pacc[1], pr[(j + 1) & 3], ya);
            ffma2(pacc[2], pr[(j + 2) & 3], ya);
            ffma2(pacc[3], pr[(j + 3) & 3], ya);
            float vlo = pr[j & 3].f.x;            // leaving element x[l0+j]
            sx2 = fmaf(vlo, vlo, sx2);
            pr[j & 3].f.x = pr[j & 3].f.y;        // pair shift
            pr[j & 3].f.y = nh;
        }
        // step j+1 (odd)
        {
            F2U yb; yb.f.x = yq.z; yb.f.y = yq.w;
            float nh = xs[padi(l0 + j + 9)];
            ffma2(pacc[0], pr[(j + 1) & 3], yb);
            ffma2(pacc[1], pr[(j + 2) & 3], yb);
            ffma2(pacc[2], pr[(j + 3) & 3], yb);
            ffma2(pacc[3], pr[(j + 4) & 3], yb);
            float vlo = pr[(j + 1) & 3].f.x;      // leaving element x[l0+j+1]
            sx2 = fmaf(vlo, vlo, sx2);
            pr[(j + 1) & 3].f.x = pr[(j + 1) & 3].f.y;
            pr[(j + 1) & 3].f.y = nh;
        }
    }
    // After loop: pr[k] = (x[l0+64+k], x[l0+68+k]), k=0..3.

    float acc[8];
    #pragma unroll
    for (int k = 0; k < 4; ++k) { acc[k] = pacc[k].f.x; acc[k + 4] = pacc[k].f.y; }

    float score[8];
    score[0] = fmaf(-2.0f, acc[0], sx2);
    float s = sx2;
    #pragma unroll
    for (int w = 1; w < 8; ++w) {
        float xin  = (w <= 4) ? pr[w - 1].f.x : pr[w - 5].f.y;  // x[l0+w+63]
        float xout = xs[padi(l0 + w - 1)];                       // x[l0+w-1]
        s = fmaf(xin, xin, s);
        s = fmaf(-xout, xout, s);
        score[w] = fmaf(-2.0f, acc[w], s);
    }

    // Thread-local tournament argmin (strict < keeps first index on ties;
    // indices ascend within a thread, so tie-break = smallest index).
    float bs = score[0];
    int   bw = 0;
    #pragma unroll
    for (int w = 1; w < 8; ++w) {
        bool better = score[w] < bs;
        bs = better ? score[w] : bs;
        bw = better ? w : bw;
    }
    if (tid == TPB - 1) bs = __int_as_float(0x7F800000); // only thread with invalid windows

    // Single monotonic pack: max over ~key == min score, tie -> smaller idx.
    unsigned long long bestik;
    {
        unsigned gidx = (unsigned)(base + l0 + bw);
        unsigned u = __float_as_uint(bs);
        unsigned m = u ^ ((unsigned)((int)u >> 31) | 0x80000000u);
        bestik = ~(((unsigned long long)m << 32) | gidx);
    }

    // Warp reduce (max over ~key)
    #pragma unroll
    for (int o = 16; o; o >>= 1) {
        unsigned long long v = __shfl_down_sync(0xFFFFFFFFu, bestik, o);
        bestik = bestik > v ? bestik : v;
    }
    if ((tid & 31) == 0) red[tid >> 5] = bestik;
    __syncthreads();

    if (tid == 0) {
        unsigned long long k = red[0];
        #pragma unroll
        for (int i = 1; i < TPB / 32; ++i) k = k > red[i] ? k : red[i];
        atomicMax(&g_best[b], k);
        __threadfence();
        unsigned prev = atomicAdd(&g_cnt[b], 1u);
        lastFlag = (prev == CHUNKS - 1) ? 1 : 0;
    }
    __syncthreads();

    // Last block for this batch gathers output and restores scratch.
    // After the fence+counter handshake, prior atomicMax results are visible;
    // a volatile read suffices (no ATOMG round-trip).
    if (lastFlag) {
        unsigned long long k = *(volatile unsigned long long*)&g_best[b];
        int start = (int)((~k) & 0xFFFFFFFFull);
        if (tid < DECL) out[b * DECL + tid] = xb[start + tid];
        __syncthreads();
        if (tid == 0) { g_best[b] = 0ULL; g_cnt[b] = 0u; }
    }
}

extern "C" void kernel_launch(void* const* d_in, const int* in_sizes, int n_in,
                              void* d_out, int out_size)
{
    // inputs: 0=feats_in (unused), 1=X_in, 2=feats_out (unused), 3=X_out
    const float* X_in  = (const float*)d_in[1];
    const float* X_out = (const float*)d_in[3];
    float* out = (float*)d_out;

    dim3 grid(CHUNKS, BATCH);
    match_kernel<<<grid, TPB>>>(X_in, X_out, out);
}